// round 2
// baseline (speedup 1.0000x reference)
#include <cuda_runtime.h>
#include <cuda_bf16.h>
#include <math.h>

#define BB 16
#define SD 512
#define DD 512
#define MT (BB*SD)      // 8192
#define NLAY 3
#define NDOM 8

// ---------------- scratch (device globals; no allocation) ----------------
__device__ float g_X[MT*DD];
__device__ float g_relX[MT*DD];
__device__ float g_fo[MT*DD];
__device__ float g_bo[MT*DD];
__device__ float g_Pf[MT*DD];
__device__ float g_Pb[MT*DD];
__device__ float g_delta[MT*DD];
__device__ float g_AxpX[MT*DD];
__device__ float g_FR[MT*DD];
__device__ float g_BR[MT*DD];
__device__ float g_outs[MT*NLAY*DD];
__device__ float g_pooled[BB*NDOM*DD];
__device__ float g_domout[BB*NDOM*DD];
__device__ float g_denom[MT];
__device__ float g_fadj[MT];
__device__ float g_badj[MT];
__device__ unsigned char g_dom8[MT*NDOM];
__device__ int g_domfmt;   // 0=uint8, 1=int32, 2=float32

__device__ __forceinline__ float sigf(float x) { return 1.f / (1.f + expf(-x)); }

// ---------------- domain dtype detection + normalization ----------------
// The `domain` input is a jax bool array; the harness ABI for bool is not
// documented. Detect encoding from content (deterministic for fixed inputs):
//   float32: words in {0x00000000, 0x3F800000}
//   int32:   words in {0, 1}
//   uint8:   packed 0/1 bytes -> many words with value > 1
__global__ void detect_dom_fmt(const unsigned int* __restrict__ w) {
    __shared__ int sf, sb;
    if (threadIdx.x == 0) { sf = 0; sb = 0; }
    __syncthreads();
    for (int i = threadIdx.x; i < 1024; i += 256) {
        unsigned int v = w[i];
        if (v == 0x3F800000u) atomicOr(&sf, 1);
        else if (v > 1u) atomicOr(&sb, 1);
    }
    __syncthreads();
    if (threadIdx.x == 0) g_domfmt = sf ? 2 : (sb ? 0 : 1);
}

__global__ void convert_dom(const void* __restrict__ dom, unsigned char* __restrict__ out) {
    int i = blockIdx.x * 256 + threadIdx.x;
    if (i >= MT * NDOM) return;
    int fmt = g_domfmt;
    unsigned char v;
    if (fmt == 0)      v = ((const unsigned char*)dom)[i] != 0;
    else if (fmt == 1) v = ((const int*)dom)[i] != 0;
    else               v = ((const float*)dom)[i] != 0.f;
    out[i] = v;
}

// ---------------- row stats: denom, frontadj, backadj ----------------
__global__ void rowstats_kernel(const float* __restrict__ adj,
                                const float* __restrict__ depmap,
                                float* __restrict__ denom,
                                float* __restrict__ fadj,
                                float* __restrict__ badj) {
    int warp = (blockIdx.x * blockDim.x + threadIdx.x) >> 5;
    int lane = threadIdx.x & 31;
    if (warp >= MT) return;
    int b = warp >> 9;
    int s = warp & 511;
    const float* arow = adj + (size_t)(b * SD + s) * SD;
    const float* drow = depmap + (size_t)(b * SD + s) * SD;
    const float* acol = adj + (size_t)b * SD * SD + s;
    float sa = 0.f, sf = 0.f, sb = 0.f;
    for (int j = lane; j < SD; j += 32) {
        float a = arow[j];
        float dp = drow[j];
        sa += a;
        sf += a * dp;
        sb += acol[(size_t)j * SD] * dp;
    }
#pragma unroll
    for (int off = 16; off > 0; off >>= 1) {
        sa += __shfl_down_sync(0xffffffffu, sa, off);
        sf += __shfl_down_sync(0xffffffffu, sf, off);
        sb += __shfl_down_sync(0xffffffffu, sb, off);
    }
    if (lane == 0) {
        denom[warp] = sa + 1.f;
        fadj[warp] = sf;
        badj[warp] = sb;
    }
}

// ---------------- copy (X init) ----------------
__global__ void copy_kernel(const float* __restrict__ src, float* __restrict__ dst, int n4) {
    int i = blockIdx.x * blockDim.x + threadIdx.x;
    if (i < n4) ((float4*)dst)[i] = ((const float4*)src)[i];
}

// ---------------- domain pooling: pooled[b,k,d] = max_s (dom? -1e4 : X) ----------------
__global__ void pool_kernel(const float* __restrict__ X,
                            const unsigned char* __restrict__ dom,
                            float* __restrict__ pooled) {
    int b = blockIdx.x;
    int d = blockIdx.y * 128 + threadIdx.x;
    float mv[NDOM];
#pragma unroll
    for (int k = 0; k < NDOM; k++) mv[k] = -3.402823466e38f;
    const float* Xb = X + (size_t)b * SD * DD;
    const unsigned long long* db = (const unsigned long long*)(dom + (size_t)b * SD * NDOM);
    for (int s = 0; s < SD; s++) {
        float x = Xb[(size_t)s * DD + d];
        unsigned long long m = db[s];
#pragma unroll
        for (int k = 0; k < NDOM; k++) {
            float v = ((m >> (8 * k)) & 0xffull) ? -10000.f : x;
            mv[k] = fmaxf(mv[k], v);
        }
    }
#pragma unroll
    for (int k = 0; k < NDOM; k++) pooled[((size_t)b * NDOM + k) * DD + d] = mv[k];
}

// ---------------- domain gate: sigmoid(pooled @ W_dg + b_dg) ----------------
__global__ void dgate_kernel(const float* __restrict__ pooled,
                             const float* __restrict__ Wdg,
                             const float* __restrict__ bdg,
                             float* __restrict__ out) {
    int bk = blockIdx.x;   // 0..127 (b*8+k)
    int d = blockIdx.y * 128 + threadIdx.x;
    __shared__ float sp[DD];
    for (int e = threadIdx.x; e < DD; e += 128) sp[e] = pooled[(size_t)bk * DD + e];
    __syncthreads();
    float acc = bdg[d];
#pragma unroll 8
    for (int e = 0; e < DD; e++) acc += sp[e] * Wdg[(size_t)e * DD + d];
    out[(size_t)bk * DD + d] = sigf(acc);
}

// ---------------- build front/back outputs ----------------
__global__ void buildfb_kernel(const float* __restrict__ X,
                               const float* __restrict__ relX,
                               const float* __restrict__ did,
                               const float* __restrict__ rid,
                               const float* __restrict__ domout,
                               float* __restrict__ fo,
                               float* __restrict__ bo) {
    int bs = blockIdx.x;          // 0..8191
    int b = bs >> 9;
    int d = threadIdx.x;          // 0..511
    __shared__ float sdi[NDOM], sri[NDOM];
    if (threadIdx.x < NDOM) sdi[threadIdx.x] = did[(size_t)bs * NDOM + threadIdx.x];
    else if (threadIdx.x < 2 * NDOM) sri[threadIdx.x - NDOM] = rid[(size_t)bs * NDOM + threadIdx.x - NDOM];
    __syncthreads();
    float dsum = 0.f, rsum = 0.f;
#pragma unroll
    for (int k = 0; k < NDOM; k++) { dsum += sdi[k]; rsum += sri[k]; }
    bool dmask = (dsum == 1.0f);
    bool rmask = (rsum == 1.0f);
    size_t idx = (size_t)bs * DD + d;
    float f = dmask ? 0.f : X[idx];
    float bv = rmask ? 0.f : relX[idx];
    const float* dob = domout + (size_t)b * NDOM * DD;
#pragma unroll
    for (int k = 0; k < NDOM; k++) {
        float dv = dob[(size_t)k * DD + d];
        f += sdi[k] * dv;
        bv += sri[k] * dv;
    }
    fo[idx] = f;
    bo[idx] = bv;
}

// ---------------- batched GEMM (per-batch 512x512x512), 64x64 tile ----------------
// C[b,i,d] = sum_j Aeff[b,i,j] * (B[b,j,d] * (BMUL? Bmul[b,j,d]:1))  (+ ADDC? Cadd : 0)
// TRANSA: Aeff[i,j] = A[j,i]
template<bool TRANSA, bool BMUL, bool ADDC>
__global__ void bgemm64(const float* __restrict__ A, const float* __restrict__ Bm,
                        const float* __restrict__ Bmul, const float* __restrict__ Cadd,
                        float* __restrict__ C) {
    __shared__ float As[16][68];
    __shared__ float Bs[16][68];
    int b = blockIdx.z;
    size_t base = (size_t)b * SD * DD;
    const float* Ab = A + base;
    const float* Bb = Bm + base;
    int i0 = blockIdx.y * 64, j0 = blockIdx.x * 64;
    int t = threadIdx.x;
    int tx = t & 15, ty = t >> 4;
    float acc[4][4];
#pragma unroll
    for (int r = 0; r < 4; r++)
#pragma unroll
        for (int c = 0; c < 4; c++) acc[r][c] = 0.f;

    for (int k0 = 0; k0 < SD; k0 += 16) {
        if (TRANSA) {
            int kr = t >> 4, ic = (t & 15) << 2;
            float4 av = *(const float4*)(Ab + (size_t)(k0 + kr) * SD + i0 + ic);
            *(float4*)&As[kr][ic] = av;
        } else {
            int lr = t >> 2, lc = (t & 3) << 2;
            float4 av = *(const float4*)(Ab + (size_t)(i0 + lr) * SD + k0 + lc);
            As[lc + 0][lr] = av.x; As[lc + 1][lr] = av.y;
            As[lc + 2][lr] = av.z; As[lc + 3][lr] = av.w;
        }
        {
            int kr = t >> 4, jc = (t & 15) << 2;
            float4 bv = *(const float4*)(Bb + (size_t)(k0 + kr) * DD + j0 + jc);
            if (BMUL) {
                float4 mv = *(const float4*)(Bmul + base + (size_t)(k0 + kr) * DD + j0 + jc);
                bv.x *= mv.x; bv.y *= mv.y; bv.z *= mv.z; bv.w *= mv.w;
            }
            *(float4*)&Bs[kr][jc] = bv;
        }
        __syncthreads();
#pragma unroll
        for (int kk = 0; kk < 16; kk++) {
            float4 a = *(const float4*)&As[kk][ty << 2];
            float4 bq = *(const float4*)&Bs[kk][tx << 2];
            float ar[4] = {a.x, a.y, a.z, a.w};
            float br[4] = {bq.x, bq.y, bq.z, bq.w};
#pragma unroll
            for (int r = 0; r < 4; r++)
#pragma unroll
                for (int c = 0; c < 4; c++) acc[r][c] = fmaf(ar[r], br[c], acc[r][c]);
        }
        __syncthreads();
    }
#pragma unroll
    for (int r = 0; r < 4; r++) {
        int row = i0 + (ty << 2) + r;
        size_t idx = base + (size_t)row * DD + j0 + (tx << 2);
        float4 v = make_float4(acc[r][0], acc[r][1], acc[r][2], acc[r][3]);
        if (ADDC) {
            float4 xa = *(const float4*)(Cadd + idx);
            v.x += xa.x; v.y += xa.y; v.z += xa.z; v.w += xa.w;
        }
        *(float4*)(C + idx) = v;
    }
}

// ---------------- weight GEMM [8192,K] x [K,512], 64x64 tile + fused epilogues ----
// EPI 0: C = acc + bias[n]                                    (FR/BR precompute)
// EPI 1: C = rowv[m] * sigmoid(acc + add1) * mulel             (gate products Pf/Pb)
// EPI 2: t=(acc + 2*bias[n] + add1 + add2)/rowv[m]; PReLU; -> C (=X) and C2 (=outs slot)
// EPI 3: C = acc + bias[n] + add1                              (final projection)
template<int EPI>
__global__ void wgemm64(const float* __restrict__ A, const float* __restrict__ W, int K,
                        float* __restrict__ C, const float* __restrict__ bias,
                        const float* __restrict__ add1, const float* __restrict__ add2,
                        const float* __restrict__ rowv, const float* __restrict__ mulel,
                        const float* __restrict__ pa, int l, float* __restrict__ C2) {
    __shared__ float As[16][68];
    __shared__ float Ws[16][68];
    int i0 = blockIdx.y * 64, j0 = blockIdx.x * 64;
    int t = threadIdx.x;
    int tx = t & 15, ty = t >> 4;
    float acc[4][4];
#pragma unroll
    for (int r = 0; r < 4; r++)
#pragma unroll
        for (int c = 0; c < 4; c++) acc[r][c] = 0.f;

    for (int k0 = 0; k0 < K; k0 += 16) {
        {
            int lr = t >> 2, lc = (t & 3) << 2;
            float4 av = *(const float4*)(A + (size_t)(i0 + lr) * K + k0 + lc);
            As[lc + 0][lr] = av.x; As[lc + 1][lr] = av.y;
            As[lc + 2][lr] = av.z; As[lc + 3][lr] = av.w;
        }
        {
            int kr = t >> 4, jc = (t & 15) << 2;
            float4 wv = *(const float4*)(W + (size_t)(k0 + kr) * DD + j0 + jc);
            *(float4*)&Ws[kr][jc] = wv;
        }
        __syncthreads();
#pragma unroll
        for (int kk = 0; kk < 16; kk++) {
            float4 a = *(const float4*)&As[kk][ty << 2];
            float4 w = *(const float4*)&Ws[kk][tx << 2];
            float ar[4] = {a.x, a.y, a.z, a.w};
            float wr[4] = {w.x, w.y, w.z, w.w};
#pragma unroll
            for (int r = 0; r < 4; r++)
#pragma unroll
                for (int c = 0; c < 4; c++) acc[r][c] = fmaf(ar[r], wr[c], acc[r][c]);
        }
        __syncthreads();
    }

    int n = j0 + (tx << 2);
#pragma unroll
    for (int r = 0; r < 4; r++) {
        int m = i0 + (ty << 2) + r;
        size_t idx = (size_t)m * DD + n;
        float v[4] = {acc[r][0], acc[r][1], acc[r][2], acc[r][3]};
        if (EPI == 0) {
#pragma unroll
            for (int c = 0; c < 4; c++) v[c] += bias[n + c];
        } else if (EPI == 1) {
            float rv = rowv[m];
            float4 a1 = *(const float4*)(add1 + idx);
            float4 me = *(const float4*)(mulel + idx);
            float a1a[4] = {a1.x, a1.y, a1.z, a1.w};
            float mea[4] = {me.x, me.y, me.z, me.w};
#pragma unroll
            for (int c = 0; c < 4; c++) v[c] = rv * sigf(v[c] + a1a[c]) * mea[c];
        } else if (EPI == 2) {
            float invd = 1.f / rowv[m];
            float al = pa[l];
            float4 a1 = *(const float4*)(add1 + idx);
            float4 a2 = *(const float4*)(add2 + idx);
            float a1a[4] = {a1.x, a1.y, a1.z, a1.w};
            float a2a[4] = {a2.x, a2.y, a2.z, a2.w};
#pragma unroll
            for (int c = 0; c < 4; c++) {
                float tt = (v[c] + 2.f * bias[n + c] + a1a[c] + a2a[c]) * invd;
                v[c] = tt >= 0.f ? tt : al * tt;
            }
            *(float4*)(C2 + (size_t)m * (NLAY * DD) + n) = make_float4(v[0], v[1], v[2], v[3]);
        } else if (EPI == 3) {
            float4 a1 = *(const float4*)(add1 + idx);
            float a1a[4] = {a1.x, a1.y, a1.z, a1.w};
#pragma unroll
            for (int c = 0; c < 4; c++) v[c] += bias[n + c] + a1a[c];
        }
        *(float4*)(C + idx) = make_float4(v[0], v[1], v[2], v[3]);
    }
}

// ---------------- host launcher ----------------
extern "C" void kernel_launch(void* const* d_in, const int* in_sizes, int n_in,
                              void* d_out, int out_size) {
    const float* adj       = (const float*)d_in[0];
    const void*  domain    = d_in[1];
    const float* domain_id = (const float*)d_in[2];
    const float* redom_id  = (const float*)d_in[3];
    const float* frontrel  = (const float*)d_in[4];
    const float* backrel   = (const float*)d_in[5];
    const float* depmap    = (const float*)d_in[6];
    const float* rel       = (const float*)d_in[7];
    const float* gcn       = (const float*)d_in[8];
    // d_in[9] = mask (unused)
    const float* W_layers  = (const float*)d_in[10];
    const float* b_layers  = (const float*)d_in[11];
    const float* prelu_a   = (const float*)d_in[12];
    const float* W_dg      = (const float*)d_in[13];
    const float* b_dg      = (const float*)d_in[14];
    const float* W_mg      = (const float*)d_in[15];
    const float* b_mg      = (const float*)d_in[16];
    const float* W_out     = (const float*)d_in[17];
    const float* b_out     = (const float*)d_in[18];

    float *X, *relX, *fo, *bo, *Pf, *Pb, *delta, *AxpX, *FR, *BR, *outs,
          *pooled, *domout, *denom, *fadj, *badj;
    unsigned char *dom8;
    cudaGetSymbolAddress((void**)&X, g_X);
    cudaGetSymbolAddress((void**)&relX, g_relX);
    cudaGetSymbolAddress((void**)&fo, g_fo);
    cudaGetSymbolAddress((void**)&bo, g_bo);
    cudaGetSymbolAddress((void**)&Pf, g_Pf);
    cudaGetSymbolAddress((void**)&Pb, g_Pb);
    cudaGetSymbolAddress((void**)&delta, g_delta);
    cudaGetSymbolAddress((void**)&AxpX, g_AxpX);
    cudaGetSymbolAddress((void**)&FR, g_FR);
    cudaGetSymbolAddress((void**)&BR, g_BR);
    cudaGetSymbolAddress((void**)&outs, g_outs);
    cudaGetSymbolAddress((void**)&pooled, g_pooled);
    cudaGetSymbolAddress((void**)&domout, g_domout);
    cudaGetSymbolAddress((void**)&denom, g_denom);
    cudaGetSymbolAddress((void**)&fadj, g_fadj);
    cudaGetSymbolAddress((void**)&badj, g_badj);
    cudaGetSymbolAddress((void**)&dom8, g_dom8);

    dim3 bgrid(8, 8, 16);     // batched 512x512 GEMMs
    dim3 wgrid(8, 128);       // [8192 x 512] weight GEMMs

    // normalize domain (bool) encoding to packed uint8
    detect_dom_fmt<<<1, 256>>>((const unsigned int*)domain);
    convert_dom<<<(MT * NDOM + 255) / 256, 256>>>(domain, dom8);

    // layer-invariant precomputes
    rowstats_kernel<<<1024, 256>>>(adj, depmap, denom, fadj, badj);
    copy_kernel<<<(MT * DD / 4 + 255) / 256, 256>>>(gcn, X, MT * DD / 4);
    // FR = frontrel @ W_mg[D:2D] + b_mg ; BR = backrel @ W_mg[D:2D] + b_mg
    wgemm64<0><<<wgrid, 256>>>(frontrel, W_mg + (size_t)DD * DD, DD, FR, b_mg,
                               nullptr, nullptr, nullptr, nullptr, nullptr, 0, nullptr);
    wgemm64<0><<<wgrid, 256>>>(backrel, W_mg + (size_t)DD * DD, DD, BR, b_mg,
                               nullptr, nullptr, nullptr, nullptr, nullptr, 0, nullptr);

    for (int l = 0; l < NLAY; l++) {
        pool_kernel<<<dim3(BB, DD / 128), 128>>>(X, dom8, pooled);
        dgate_kernel<<<dim3(BB * NDOM, DD / 128), 128>>>(pooled, W_dg, b_dg, domout);
        // relX = rel @ X
        bgemm64<false, false, false><<<bgrid, 256>>>(rel, X, nullptr, nullptr, relX);
        buildfb_kernel<<<MT, 512>>>(X, relX, domain_id, redom_id, domout, fo, bo);
        // Pf = frontadj * sigmoid(fo @ W_mg[:D] + FR) * fo ; Pb analogous
        wgemm64<1><<<wgrid, 256>>>(fo, W_mg, DD, Pf, nullptr, FR, nullptr, fadj, fo,
                                   nullptr, 0, nullptr);
        wgemm64<1><<<wgrid, 256>>>(bo, W_mg, DD, Pb, nullptr, BR, nullptr, badj, bo,
                                   nullptr, 0, nullptr);
        // delta = rel^T @ Pf
        bgemm64<true, false, false><<<bgrid, 256>>>(rel, Pf, nullptr, nullptr, delta);
        // AxpX = adj @ (X * rel) + X
        bgemm64<false, true, true><<<bgrid, 256>>>(adj, X, rel, X, AxpX);
        // X = PReLU((AxpX @ W_l + 2*b_l + delta + Pb)/denom); also store into outs[:, l*D:]
        wgemm64<2><<<wgrid, 256>>>(AxpX, W_layers + (size_t)l * DD * DD, DD, X,
                                   b_layers + (size_t)l * DD, delta, Pb, denom,
                                   nullptr, prelu_a, l, outs + (size_t)l * DD);
    }
    // final: out = outs @ W_out + b_out + gcn_inputs
    wgemm64<3><<<wgrid, 256>>>(outs, W_out, NLAY * DD, (float*)d_out, b_out, gcn,
                               nullptr, nullptr, nullptr, nullptr, 0, nullptr);
}